// round 7
// baseline (speedup 1.0000x reference)
#include <cuda_runtime.h>

#define NN 50000
#define EE 800000
#define ETOT (EE + NN)
#define F 128
#define NG 64
#define NOUT 10

// ---------------- device scratch (static, no allocation) ----------------
static __device__ __align__(16) int   g_deg[NN];
static __device__ __align__(16) int   g_fill[NN];
static __device__ __align__(16) int   g_rowstart[NN + 1];
static __device__ __align__(16) int   g_csr[ETOT];
static __device__ __align__(16) int   g_cdst[ETOT];
static __device__ __align__(16) float g_p[ETOT * 4];     // per-edge exp factors (4 heads)
static __device__ __align__(16) float g_h[NN * F];       // post-GEMM features
static __device__ __align__(16) float g_o[NN * F];       // layer-1 aggregated output
static __device__ __align__(16) float g_als[NN * 4];
static __device__ __align__(16) float g_ald[NN * 4];
static __device__ __align__(16) float g_pool[NG * F];
static __device__ __align__(16) int   g_cnt[NG];

__device__ __forceinline__ float lrelu(float x) { return x > 0.f ? x : 0.2f * x; }

// packed fp32x2 FMA (Blackwell FFMA2: 2 exact fp32 FMAs per instruction)
__device__ __forceinline__ unsigned long long fma2(unsigned long long a,
                                                   unsigned long long b,
                                                   unsigned long long c) {
    unsigned long long d;
    asm("fma.rn.f32x2 %0, %1, %2, %3;" : "=l"(d) : "l"(a), "l"(b), "l"(c));
    return d;
}
__device__ __forceinline__ float2 unpack2(unsigned long long v) {
    float2 r;
    asm("mov.b64 {%0, %1}, %2;" : "=f"(r.x), "=f"(r.y) : "l"(v));
    return r;
}
struct __align__(16) ull2 { unsigned long long x, y; };

// ---------------- zero scratch ----------------
__global__ void k_zero() {
    int i = blockIdx.x * blockDim.x + threadIdx.x;
    if (i < NN) { g_deg[i] = 0; g_fill[i] = 0; }
    if (i < NG * F) g_pool[i] = 0.f;
    if (i < NG) g_cnt[i] = 0;
}

// ---------------- degree histogram + graph-size histogram (ILP-4) ----------------
__global__ void k_degree(const int* __restrict__ dst, const int* __restrict__ batch) {
    int stride = gridDim.x * blockDim.x;
    int i = blockIdx.x * blockDim.x + threadIdx.x;
    #pragma unroll
    for (int u = 0; u < 4; u++, i += stride) {
        if (i < ETOT) {
            int d = (i < EE) ? dst[i] : (i - EE);   // self loops appended
            atomicAdd(&g_deg[d], 1);
        }
        if (i < NN) atomicAdd(&g_cnt[batch[i]], 1);
    }
}

// ---------------- raking single-block exclusive scan (1024 thr, 64 elem/thr) ----------------
__global__ void k_scan() {
    const int CH = 64;
    int t = threadIdx.x;
    int wid = t >> 5, lane = t & 31;
    __shared__ int wsum[32];
    int base = t * CH;

    int s = 0;
    if (base + CH <= NN) {
        const int4* p = (const int4*)&g_deg[base];
        #pragma unroll
        for (int k = 0; k < CH / 4; k++) { int4 v = p[k]; s += v.x + v.y + v.z + v.w; }
    } else if (base < NN) {
        for (int k = 0; k < CH && base + k < NN; k++) s += g_deg[base + k];
    }
    int incl = s;
    #pragma unroll
    for (int off = 1; off < 32; off <<= 1) {
        int v = __shfl_up_sync(0xffffffffu, incl, off);
        if (lane >= off) incl += v;
    }
    if (lane == 31) wsum[wid] = incl;
    __syncthreads();
    if (wid == 0) {
        int v = wsum[lane];
        int iv = v;
        #pragma unroll
        for (int off = 1; off < 32; off <<= 1) {
            int u = __shfl_up_sync(0xffffffffu, iv, off);
            if (lane >= off) iv += u;
        }
        wsum[lane] = iv - v;
    }
    __syncthreads();
    int run = wsum[wid] + (incl - s);
    if (base < NN) {
        int lim = (base + CH <= NN) ? CH : (NN - base);
        for (int k = 0; k < lim; k++) {
            int v = g_deg[base + k];
            g_rowstart[base + k] = run;
            run += v;
        }
    }
    if (t == 0) g_rowstart[NN] = ETOT;
}

// ---------------- CSR scatter (ILP-4) ----------------
__global__ void k_scatter(const int* __restrict__ src, const int* __restrict__ dst) {
    int stride = gridDim.x * blockDim.x;
    int i = blockIdx.x * blockDim.x + threadIdx.x;
    #pragma unroll
    for (int u = 0; u < 4; u++, i += stride) {
        if (i < ETOT) {
            int s, d;
            if (i < EE) { s = src[i]; d = dst[i]; }
            else        { s = i - EE; d = s; }
            int slot = g_rowstart[d] + atomicAdd(&g_fill[d], 1);
            g_csr[slot] = s;
            g_cdst[slot] = d;
        }
    }
}

// ---------------- GEMM g_h = A @ B with packed f32x2 FMA + fused coeff epilogue ----
// BLOCK_M=64, BK=16, 256 threads; thread computes 8 rows x 4 cols (as 8x2 pairs).
__global__ void __launch_bounds__(256) k_gemm(const float* __restrict__ Aext,
                                              const float* __restrict__ B,
                                              const float* __restrict__ asrc,
                                              const float* __restrict__ adst,
                                              int use_go) {
    const float* __restrict__ A = use_go ? (const float*)g_o : Aext;
    __shared__ float2 As2[64][16];   // a-values pre-duplicated: (a,a)
    __shared__ float4 Bs4[16][32];   // b row pairs: .xy / .zw are natural b64 pairs
    int t = threadIdx.x;
    int base = blockIdx.x * 64;
    int tx = t & 31;
    int ty = t >> 5;

    unsigned long long acc[8][2];
    #pragma unroll
    for (int i = 0; i < 8; i++) { acc[i][0] = 0ull; acc[i][1] = 0ull; }

    int lrow = t >> 2;         // 0..63
    int lq = (t & 3) * 4;      // 0,4,8,12
    int grow = base + lrow;

    for (int k0 = 0; k0 < 128; k0 += 16) {
        float4 av = make_float4(0.f, 0.f, 0.f, 0.f);
        if (grow < NN) av = *(const float4*)&A[grow * F + k0 + lq];
        As2[lrow][lq + 0] = make_float2(av.x, av.x);
        As2[lrow][lq + 1] = make_float2(av.y, av.y);
        As2[lrow][lq + 2] = make_float2(av.z, av.z);
        As2[lrow][lq + 3] = make_float2(av.w, av.w);
        int f0 = t * 2;
        #pragma unroll
        for (int u = 0; u < 2; u++) {
            int f = f0 + u;
            int kr = f >> 5;          // 0..15
            int c  = f & 31;          // float4 col group
            Bs4[kr][c] = *(const float4*)&B[(k0 + kr) * F + c * 4];
        }
        __syncthreads();
        #pragma unroll
        for (int kk = 0; kk < 16; kk++) {
            ull2 bq = *(const ull2*)&Bs4[kk][tx];
            #pragma unroll
            for (int i = 0; i < 8; i++) {
                unsigned long long aa =
                    *(const unsigned long long*)&As2[ty * 8 + i][kk];  // broadcast LDS.64
                acc[i][0] = fma2(aa, bq.x, acc[i][0]);
                acc[i][1] = fma2(aa, bq.y, acc[i][1]);
            }
        }
        __syncthreads();
    }

    // epilogue: write h; reduce als/ald per head (heads = lane groups of 8)
    float wsr[4], wdr[4];
    #pragma unroll
    for (int j = 0; j < 4; j++) { wsr[j] = asrc[tx * 4 + j]; wdr[j] = adst[tx * 4 + j]; }
    int hd = tx >> 3;
    #pragma unroll
    for (int i = 0; i < 8; i++) {
        int r = base + ty * 8 + i;
        float2 c01 = unpack2(acc[i][0]);
        float2 c23 = unpack2(acc[i][1]);
        float ss = 0.f, sd = 0.f;
        ss = fmaf(c01.x, wsr[0], ss); sd = fmaf(c01.x, wdr[0], sd);
        ss = fmaf(c01.y, wsr[1], ss); sd = fmaf(c01.y, wdr[1], sd);
        ss = fmaf(c23.x, wsr[2], ss); sd = fmaf(c23.x, wdr[2], sd);
        ss = fmaf(c23.y, wsr[3], ss); sd = fmaf(c23.y, wdr[3], sd);
        #pragma unroll
        for (int off = 4; off; off >>= 1) {
            ss += __shfl_xor_sync(0xffffffffu, ss, off);
            sd += __shfl_xor_sync(0xffffffffu, sd, off);
        }
        if (r < NN) {
            *(float4*)&g_h[r * F + tx * 4] = make_float4(c01.x, c01.y, c23.x, c23.y);
            if ((tx & 7) == 0) {
                g_als[r * 4 + hd] = ss;
                g_ald[r * 4 + hd] = sd;
            }
        }
    }
}

// ---------------- per-edge exp factors (ILP-2; no max shift, |e| small) ----------------
__global__ void k_edgep() {
    int stride = gridDim.x * blockDim.x;
    int i = blockIdx.x * blockDim.x + threadIdx.x;
    #pragma unroll
    for (int u = 0; u < 2; u++, i += stride) {
        if (i >= ETOT) continue;
        int s = g_csr[i];
        int d = g_cdst[i];
        float4 as = *(const float4*)&g_als[s * 4];
        float4 ad = *(const float4*)&g_ald[d * 4];
        float4 p;
        p.x = __expf(lrelu(as.x + ad.x));
        p.y = __expf(lrelu(as.y + ad.y));
        p.z = __expf(lrelu(as.z + ad.z));
        p.w = __expf(lrelu(as.w + ad.w));
        *(float4*)&g_p[i * 4] = p;
    }
}

// ---------------- fused aggregation (warp per dst); single pass, precomputed p ----------------
__global__ void k_agg(const float* __restrict__ bias, const int* __restrict__ batch,
                      int apply_elu, int do_pool) {
    int node = (blockIdx.x * blockDim.x + threadIdx.x) >> 5;
    int lane = threadIdx.x & 31;
    if (node >= NN) return;
    int beg = g_rowstart[node];
    int end = g_rowstart[node + 1];

    float z0 = 0.f, z1 = 0.f, z2 = 0.f, z3 = 0.f;
    float a0 = 0.f, a1 = 0.f, a2 = 0.f, a3 = 0.f;
    int j = beg;
    for (; j + 2 <= end; j += 2) {
        int s0 = g_csr[j];
        int s1 = g_csr[j + 1];
        float4 p0 = *(const float4*)&g_p[j * 4];
        float4 p1 = *(const float4*)&g_p[(j + 1) * 4];
        const float* h0 = g_h + s0 * F;
        const float* h1 = g_h + s1 * F;
        float x00 = h0[lane], x01 = h0[32 + lane], x02 = h0[64 + lane], x03 = h0[96 + lane];
        float x10 = h1[lane], x11 = h1[32 + lane], x12 = h1[64 + lane], x13 = h1[96 + lane];
        z0 += p0.x + p1.x; z1 += p0.y + p1.y; z2 += p0.z + p1.z; z3 += p0.w + p1.w;
        a0 = fmaf(x00, p0.x, fmaf(x10, p1.x, a0));
        a1 = fmaf(x01, p0.y, fmaf(x11, p1.y, a1));
        a2 = fmaf(x02, p0.z, fmaf(x12, p1.z, a2));
        a3 = fmaf(x03, p0.w, fmaf(x13, p1.w, a3));
    }
    if (j < end) {
        int s0 = g_csr[j];
        float4 p0 = *(const float4*)&g_p[j * 4];
        const float* h0 = g_h + s0 * F;
        z0 += p0.x; z1 += p0.y; z2 += p0.z; z3 += p0.w;
        a0 = fmaf(h0[lane],      p0.x, a0);
        a1 = fmaf(h0[32 + lane], p0.y, a1);
        a2 = fmaf(h0[64 + lane], p0.z, a2);
        a3 = fmaf(h0[96 + lane], p0.w, a3);
    }

    float o0 = a0 / (z0 + 1e-16f) + bias[lane];
    float o1 = a1 / (z1 + 1e-16f) + bias[32 + lane];
    float o2 = a2 / (z2 + 1e-16f) + bias[64 + lane];
    float o3 = a3 / (z3 + 1e-16f) + bias[96 + lane];
    if (apply_elu) {
        o0 = o0 > 0.f ? o0 : __expf(o0) - 1.f;
        o1 = o1 > 0.f ? o1 : __expf(o1) - 1.f;
        o2 = o2 > 0.f ? o2 : __expf(o2) - 1.f;
        o3 = o3 > 0.f ? o3 : __expf(o3) - 1.f;
    }
    if (do_pool) {
        int g = batch[node];
        float* pp = g_pool + g * F;
        atomicAdd(&pp[lane],      o0);
        atomicAdd(&pp[32 + lane], o1);
        atomicAdd(&pp[64 + lane], o2);
        atomicAdd(&pp[96 + lane], o3);
    } else {
        float* op = g_o + node * F;
        op[lane]      = o0;
        op[32 + lane] = o1;
        op[64 + lane] = o2;
        op[96 + lane] = o3;
    }
}

// ---------------- final linear + softmax (warp per graph) ----------------
__global__ void k_final(const float* __restrict__ Wl, const float* __restrict__ bl,
                        float* __restrict__ out) {
    int g = (blockIdx.x * blockDim.x + threadIdx.x) >> 5;
    int lane = threadIdx.x & 31;
    if (g >= NG) return;
    float inv = 1.f / fmaxf((float)g_cnt[g], 1.f);
    float logit = -1e30f;
    if (lane < NOUT) {
        float acc = bl[lane];
        for (int c = 0; c < F; c++)
            acc = fmaf(g_pool[g * F + c] * inv, Wl[c * NOUT + lane], acc);
        logit = acc;
    }
    float mx = logit;
    #pragma unroll
    for (int off = 16; off; off >>= 1) mx = fmaxf(mx, __shfl_xor_sync(0xffffffffu, mx, off));
    float ex = (lane < NOUT) ? __expf(logit - mx) : 0.f;
    float s = ex;
    #pragma unroll
    for (int off = 16; off; off >>= 1) s += __shfl_xor_sync(0xffffffffu, s, off);
    if (lane < NOUT) out[g * NOUT + lane] = ex / s;
}

// ---------------- launch ----------------
extern "C" void kernel_launch(void* const* d_in, const int* in_sizes, int n_in,
                              void* d_out, int out_size) {
    const float* x    = (const float*)d_in[0];
    const float* W1   = (const float*)d_in[1];
    const float* a1s  = (const float*)d_in[2];
    const float* a1d  = (const float*)d_in[3];
    const float* b1   = (const float*)d_in[4];
    const float* W2   = (const float*)d_in[5];
    const float* a2s  = (const float*)d_in[6];
    const float* a2d  = (const float*)d_in[7];
    const float* b2   = (const float*)d_in[8];
    const float* Wl   = (const float*)d_in[9];
    const float* bl   = (const float*)d_in[10];
    const int*   ei   = (const int*)d_in[11];
    const int*   batch = (const int*)d_in[12];
    const int* src = ei;
    const int* dst = ei + EE;
    float* out = (float*)d_out;

    // CSR build
    k_zero<<<(NN + 255) / 256, 256>>>();
    k_degree<<<(ETOT + 1023) / 1024, 256>>>(dst, batch);
    k_scan<<<1, 1024>>>();
    k_scatter<<<(ETOT + 1023) / 1024, 256>>>(src, dst);

    int gemm_blocks = (NN + 63) / 64;
    int warp_blocks = (NN * 32 + 255) / 256;
    int edge2_blocks = (ETOT + 511) / 512;

    // layer 1
    k_gemm<<<gemm_blocks, 256>>>(x, W1, a1s, a1d, 0);
    k_edgep<<<edge2_blocks, 256>>>();
    k_agg<<<warp_blocks, 256>>>(b1, batch, 1, 0);

    // layer 2 (aggregation pools directly)
    k_gemm<<<gemm_blocks, 256>>>(nullptr, W2, a2s, a2d, 1);
    k_edgep<<<edge2_blocks, 256>>>();
    k_agg<<<warp_blocks, 256>>>(b2, batch, 0, 1);

    // head
    k_final<<<(NG * 32 + 255) / 256, 256>>>(Wl, bl, out);
}

// round 8
// speedup vs baseline: 1.1495x; 1.1495x over previous
#include <cuda_runtime.h>

#define NN 50000
#define EE 800000
#define ETOT (EE + NN)
#define F 128
#define NG 64
#define NOUT 10
#define GEMM_BLOCKS ((NN + 63) / 64)
#define DEG_BLOCKS ((ETOT + 255) / 256)

// ---------------- device scratch (static, no allocation) ----------------
static __device__ __align__(16) int   g_deg[NN];
static __device__ __align__(16) int   g_fill[NN];
static __device__ __align__(16) int   g_rowstart[NN + 1];
static __device__ __align__(16) int2  g_edge[ETOT];      // (src, dst) per CSR slot
static __device__ __align__(16) float g_p[ETOT * 4];     // per-edge exp factors (4 heads)
static __device__ __align__(16) float g_h[NN * F];       // post-GEMM features
static __device__ __align__(16) float g_o[NN * F];       // layer-1 aggregated output
static __device__ __align__(16) float g_als[NN * 4];
static __device__ __align__(16) float g_ald[NN * 4];
static __device__ __align__(16) float g_pool[NG * F];
static __device__ __align__(16) int   g_cnt[NG];

__device__ __forceinline__ float lrelu(float x) { return x > 0.f ? x : 0.2f * x; }

// ---------------- zero scratch ----------------
__global__ void k_zero() {
    int i = blockIdx.x * blockDim.x + threadIdx.x;
    if (i < NN) { g_deg[i] = 0; g_fill[i] = 0; }
    if (i < NG * F) g_pool[i] = 0.f;
    if (i < NG) g_cnt[i] = 0;
}

// ---------------- raking single-block exclusive scan (1024 thr, 64 elem/thr) ----------------
__global__ void k_scan() {
    const int CH = 64;
    int t = threadIdx.x;
    int wid = t >> 5, lane = t & 31;
    __shared__ int wsum[32];
    int base = t * CH;

    int s = 0;
    if (base + CH <= NN) {
        const int4* p = (const int4*)&g_deg[base];
        #pragma unroll
        for (int k = 0; k < CH / 4; k++) { int4 v = p[k]; s += v.x + v.y + v.z + v.w; }
    } else if (base < NN) {
        for (int k = 0; k < CH && base + k < NN; k++) s += g_deg[base + k];
    }
    int incl = s;
    #pragma unroll
    for (int off = 1; off < 32; off <<= 1) {
        int v = __shfl_up_sync(0xffffffffu, incl, off);
        if (lane >= off) incl += v;
    }
    if (lane == 31) wsum[wid] = incl;
    __syncthreads();
    if (wid == 0) {
        int v = wsum[lane];
        int iv = v;
        #pragma unroll
        for (int off = 1; off < 32; off <<= 1) {
            int u = __shfl_up_sync(0xffffffffu, iv, off);
            if (lane >= off) iv += u;
        }
        wsum[lane] = iv - v;
    }
    __syncthreads();
    int run = wsum[wid] + (incl - s);
    if (base < NN) {
        int lim = (base + CH <= NN) ? CH : (NN - base);
        for (int k = 0; k < lim; k++) {
            int v = g_deg[base + k];
            g_rowstart[base + k] = run;
            run += v;
        }
    }
    if (t == 0) g_rowstart[NN] = ETOT;
}

// ---------------- CSR scatter: one STG.64 per edge ----------------
__global__ void k_scatter(const int* __restrict__ src, const int* __restrict__ dst) {
    int i = blockIdx.x * blockDim.x + threadIdx.x;
    if (i >= ETOT) return;
    int s, d;
    if (i < EE) { s = src[i]; d = dst[i]; }
    else        { s = i - EE; d = s; }
    int slot = g_rowstart[d] + atomicAdd(&g_fill[d], 1);
    g_edge[slot] = make_int2(s, d);
}

// ---------------- GEMM g_h = A @ B + fused coeff epilogue (+ optional degree tail) ----
// Blocks [0, GEMM_BLOCKS): GEMM (BLOCK_M=64, BK=16, 256 thr, 8x4 per thread).
// Blocks [GEMM_BLOCKS, +DEG_BLOCKS): degree + graph-count histograms (layer 1 only).
__global__ void __launch_bounds__(256) k_gemm(const float* __restrict__ Aext,
                                              const float* __restrict__ B,
                                              const float* __restrict__ asrc,
                                              const float* __restrict__ adst,
                                              const int* __restrict__ dst,
                                              const int* __restrict__ batch,
                                              int use_go) {
    if (blockIdx.x >= GEMM_BLOCKS) {
        // ---- degree histogram companion (runs concurrently with GEMM blocks) ----
        int i = (blockIdx.x - GEMM_BLOCKS) * blockDim.x + threadIdx.x;
        if (i < ETOT) {
            int d = (i < EE) ? dst[i] : (i - EE);   // self loops appended
            atomicAdd(&g_deg[d], 1);
        }
        if (i < NN) atomicAdd(&g_cnt[batch[i]], 1);
        return;
    }

    const float* __restrict__ A = use_go ? (const float*)g_o : Aext;
    __shared__ float As[64][16];
    __shared__ float Bs[16][128];
    int t = threadIdx.x;
    int base = blockIdx.x * 64;
    int tx = t & 31;
    int ty = t >> 5;

    float acc[8][4];
    #pragma unroll
    for (int i = 0; i < 8; i++)
        #pragma unroll
        for (int j = 0; j < 4; j++) acc[i][j] = 0.f;

    int lrow = t >> 2;
    int lq = (t & 3) * 4;
    int grow = base + lrow;

    for (int k0 = 0; k0 < 128; k0 += 16) {
        float4 av = make_float4(0.f, 0.f, 0.f, 0.f);
        if (grow < NN) av = *(const float4*)&A[grow * F + k0 + lq];
        *(float4*)&As[lrow][lq] = av;
        int f0 = t * 2;
        #pragma unroll
        for (int u = 0; u < 2; u++) {
            int f = f0 + u;
            int kr = f >> 5;
            int c4 = (f & 31) * 4;
            *(float4*)&Bs[kr][c4] = *(const float4*)&B[(k0 + kr) * F + c4];
        }
        __syncthreads();
        #pragma unroll
        for (int kk = 0; kk < 16; kk++) {
            float4 bv = *(float4*)&Bs[kk][tx * 4];
            #pragma unroll
            for (int i = 0; i < 8; i++) {
                float a = As[ty * 8 + i][kk];
                acc[i][0] = fmaf(a, bv.x, acc[i][0]);
                acc[i][1] = fmaf(a, bv.y, acc[i][1]);
                acc[i][2] = fmaf(a, bv.z, acc[i][2]);
                acc[i][3] = fmaf(a, bv.w, acc[i][3]);
            }
        }
        __syncthreads();
    }

    // epilogue: write h; reduce als/ald per head (heads = lane groups of 8)
    float wsr[4], wdr[4];
    #pragma unroll
    for (int j = 0; j < 4; j++) { wsr[j] = asrc[tx * 4 + j]; wdr[j] = adst[tx * 4 + j]; }
    int hd = tx >> 3;
    #pragma unroll
    for (int i = 0; i < 8; i++) {
        int r = base + ty * 8 + i;
        float ss = 0.f, sd = 0.f;
        #pragma unroll
        for (int j = 0; j < 4; j++) {
            ss = fmaf(acc[i][j], wsr[j], ss);
            sd = fmaf(acc[i][j], wdr[j], sd);
        }
        #pragma unroll
        for (int off = 4; off; off >>= 1) {
            ss += __shfl_xor_sync(0xffffffffu, ss, off);
            sd += __shfl_xor_sync(0xffffffffu, sd, off);
        }
        if (r < NN) {
            *(float4*)&g_h[r * F + tx * 4] =
                make_float4(acc[i][0], acc[i][1], acc[i][2], acc[i][3]);
            if ((tx & 7) == 0) {
                g_als[r * 4 + hd] = ss;
                g_ald[r * 4 + hd] = sd;
            }
        }
    }
}

// ---------------- per-edge exp factors (no max shift; |e| is small by construction) ----------------
__global__ void k_edgep() {
    int i = blockIdx.x * blockDim.x + threadIdx.x;
    if (i >= ETOT) return;
    int2 e = g_edge[i];              // coalesced LDG.64
    float4 as = *(const float4*)&g_als[e.x * 4];
    float4 ad = *(const float4*)&g_ald[e.y * 4];   // CSR-sorted: broadcast-friendly
    float4 p;
    p.x = __expf(lrelu(as.x + ad.x));
    p.y = __expf(lrelu(as.y + ad.y));
    p.z = __expf(lrelu(as.z + ad.z));
    p.w = __expf(lrelu(as.w + ad.w));
    *(float4*)&g_p[i * 4] = p;
}

// ---------------- fused aggregation (warp per dst); single pass, precomputed p ----------------
__global__ void k_agg(const float* __restrict__ bias, const int* __restrict__ batch,
                      int apply_elu, int do_pool) {
    int node = (blockIdx.x * blockDim.x + threadIdx.x) >> 5;
    int lane = threadIdx.x & 31;
    if (node >= NN) return;
    int beg = g_rowstart[node];
    int end = g_rowstart[node + 1];

    float z0 = 0.f, z1 = 0.f, z2 = 0.f, z3 = 0.f;
    float a0 = 0.f, a1 = 0.f, a2 = 0.f, a3 = 0.f;
    int j = beg;
    for (; j + 2 <= end; j += 2) {
        int s0 = g_edge[j].x;
        int s1 = g_edge[j + 1].x;
        float4 p0 = *(const float4*)&g_p[j * 4];
        float4 p1 = *(const float4*)&g_p[(j + 1) * 4];
        const float* h0 = g_h + s0 * F;
        const float* h1 = g_h + s1 * F;
        float x00 = h0[lane], x01 = h0[32 + lane], x02 = h0[64 + lane], x03 = h0[96 + lane];
        float x10 = h1[lane], x11 = h1[32 + lane], x12 = h1[64 + lane], x13 = h1[96 + lane];
        z0 += p0.x + p1.x; z1 += p0.y + p1.y; z2 += p0.z + p1.z; z3 += p0.w + p1.w;
        a0 = fmaf(x00, p0.x, fmaf(x10, p1.x, a0));
        a1 = fmaf(x01, p0.y, fmaf(x11, p1.y, a1));
        a2 = fmaf(x02, p0.z, fmaf(x12, p1.z, a2));
        a3 = fmaf(x03, p0.w, fmaf(x13, p1.w, a3));
    }
    if (j < end) {
        int s0 = g_edge[j].x;
        float4 p0 = *(const float4*)&g_p[j * 4];
        const float* h0 = g_h + s0 * F;
        z0 += p0.x; z1 += p0.y; z2 += p0.z; z3 += p0.w;
        a0 = fmaf(h0[lane],      p0.x, a0);
        a1 = fmaf(h0[32 + lane], p0.y, a1);
        a2 = fmaf(h0[64 + lane], p0.z, a2);
        a3 = fmaf(h0[96 + lane], p0.w, a3);
    }

    float o0 = a0 / (z0 + 1e-16f) + bias[lane];
    float o1 = a1 / (z1 + 1e-16f) + bias[32 + lane];
    float o2 = a2 / (z2 + 1e-16f) + bias[64 + lane];
    float o3 = a3 / (z3 + 1e-16f) + bias[96 + lane];
    if (apply_elu) {
        o0 = o0 > 0.f ? o0 : __expf(o0) - 1.f;
        o1 = o1 > 0.f ? o1 : __expf(o1) - 1.f;
        o2 = o2 > 0.f ? o2 : __expf(o2) - 1.f;
        o3 = o3 > 0.f ? o3 : __expf(o3) - 1.f;
    }
    if (do_pool) {
        int g = batch[node];
        float* pp = g_pool + g * F;
        atomicAdd(&pp[lane],      o0);
        atomicAdd(&pp[32 + lane], o1);
        atomicAdd(&pp[64 + lane], o2);
        atomicAdd(&pp[96 + lane], o3);
    } else {
        float* op = g_o + node * F;
        op[lane]      = o0;
        op[32 + lane] = o1;
        op[64 + lane] = o2;
        op[96 + lane] = o3;
    }
}

// ---------------- final linear + softmax (warp per graph) ----------------
__global__ void k_final(const float* __restrict__ Wl, const float* __restrict__ bl,
                        float* __restrict__ out) {
    int g = (blockIdx.x * blockDim.x + threadIdx.x) >> 5;
    int lane = threadIdx.x & 31;
    if (g >= NG) return;
    float inv = 1.f / fmaxf((float)g_cnt[g], 1.f);
    float logit = -1e30f;
    if (lane < NOUT) {
        float acc = bl[lane];
        for (int c = 0; c < F; c++)
            acc = fmaf(g_pool[g * F + c] * inv, Wl[c * NOUT + lane], acc);
        logit = acc;
    }
    float mx = logit;
    #pragma unroll
    for (int off = 16; off; off >>= 1) mx = fmaxf(mx, __shfl_xor_sync(0xffffffffu, mx, off));
    float ex = (lane < NOUT) ? __expf(logit - mx) : 0.f;
    float s = ex;
    #pragma unroll
    for (int off = 16; off; off >>= 1) s += __shfl_xor_sync(0xffffffffu, s, off);
    if (lane < NOUT) out[g * NOUT + lane] = ex / s;
}

// ---------------- launch ----------------
extern "C" void kernel_launch(void* const* d_in, const int* in_sizes, int n_in,
                              void* d_out, int out_size) {
    const float* x    = (const float*)d_in[0];
    const float* W1   = (const float*)d_in[1];
    const float* a1s  = (const float*)d_in[2];
    const float* a1d  = (const float*)d_in[3];
    const float* b1   = (const float*)d_in[4];
    const float* W2   = (const float*)d_in[5];
    const float* a2s  = (const float*)d_in[6];
    const float* a2d  = (const float*)d_in[7];
    const float* b2   = (const float*)d_in[8];
    const float* Wl   = (const float*)d_in[9];
    const float* bl   = (const float*)d_in[10];
    const int*   ei   = (const int*)d_in[11];
    const int*   batch = (const int*)d_in[12];
    const int* src = ei;
    const int* dst = ei + EE;
    float* out = (float*)d_out;

    int warp_blocks = (NN * 32 + 255) / 256;
    int edge_blocks = (ETOT + 255) / 256;

    // zero scratch, then layer-1 GEMM fused with degree histogram (independent data)
    k_zero<<<(NN + 255) / 256, 256>>>();
    k_gemm<<<GEMM_BLOCKS + DEG_BLOCKS, 256>>>(x, W1, a1s, a1d, dst, batch, 0);

    // CSR finalize
    k_scan<<<1, 1024>>>();
    k_scatter<<<(ETOT + 255) / 256, 256>>>(src, dst);

    // layer 1 edge softmax + aggregation
    k_edgep<<<edge_blocks, 256>>>();
    k_agg<<<warp_blocks, 256>>>(b1, batch, 1, 0);

    // layer 2 (aggregation pools directly)
    k_gemm<<<GEMM_BLOCKS, 256>>>(nullptr, W2, a2s, a2d, dst, batch, 1);
    k_edgep<<<edge_blocks, 256>>>();
    k_agg<<<warp_blocks, 256>>>(b2, batch, 0, 1);

    // head
    k_final<<<(NG * 32 + 255) / 256, 256>>>(Wl, bl, out);
}